// round 16
// baseline (speedup 1.0000x reference)
#include <cuda_runtime.h>
#include <cuda_fp16.h>
#include <stdint.h>
#include <math.h>

// ---------------------------------------------------------------------------
// Problem constants
// ---------------------------------------------------------------------------
#define TOK      16384
#define DMODEL   2048
#define E3       6144
#define NHEAD    16
#define HD       128
#define SEQ      64
#define NBATCH   256

// Scratch (device globals: allocation rules forbid cudaMalloc)
__device__ __half g_qkvh[(size_t)TOK * E3];         // GEMM1 out, fp16
__device__ __half g_att[(size_t)TOK * DMODEL];      // attention out, fp16
__device__ __half g_xh [(size_t)TOK * DMODEL];      // x -> fp16
__device__ __half g_wqh[(size_t)E3  * DMODEL];      // W_qkv -> fp16
__device__ __half g_woh[(size_t)DMODEL * DMODEL];   // W_out -> fp16

// ---------------------------------------------------------------------------
// fp32 -> fp16 (rn) conversion
// ---------------------------------------------------------------------------
__global__ void __launch_bounds__(256)
f2h_kernel(const float4* __restrict__ in, uint2* __restrict__ out, int n4)
{
    int i = blockIdx.x * blockDim.x + threadIdx.x;
    if (i < n4) {
        float4 v = in[i];
        __half2 h0 = __floats2half2_rn(v.x, v.y);
        __half2 h1 = __floats2half2_rn(v.z, v.w);
        uint2 u;
        u.x = *(uint32_t*)&h0;
        u.y = *(uint32_t*)&h1;
        out[i] = u;
    }
}

// ---------------------------------------------------------------------------
// Common PTX helpers
// ---------------------------------------------------------------------------
__device__ __forceinline__ void cp16(uint32_t dst, const __half* src) {
    asm volatile("cp.async.cg.shared.global [%0], [%1], 16;\n" :: "r"(dst), "l"(src));
}
__device__ __forceinline__ void cp_commit() {
    asm volatile("cp.async.commit_group;\n");
}
__device__ __forceinline__ void ldsm4(uint32_t (&r)[4], uint32_t addr) {
    asm volatile("ldmatrix.sync.aligned.m8n8.x4.shared.b16 {%0,%1,%2,%3}, [%4];\n"
                 : "=r"(r[0]), "=r"(r[1]), "=r"(r[2]), "=r"(r[3]) : "r"(addr));
}
__device__ __forceinline__ void ldsm4t(uint32_t (&r)[4], uint32_t addr) {
    asm volatile("ldmatrix.sync.aligned.m8n8.x4.trans.shared.b16 {%0,%1,%2,%3}, [%4];\n"
                 : "=r"(r[0]), "=r"(r[1]), "=r"(r[2]), "=r"(r[3]) : "r"(addr));
}
__device__ __forceinline__ void mma_f16(float (&c)[4], const uint32_t (&a)[4],
                                        uint32_t b0, uint32_t b1) {
    asm volatile(
        "mma.sync.aligned.m16n8k16.row.col.f32.f16.f16.f32 "
        "{%0,%1,%2,%3},{%4,%5,%6,%7},{%8,%9},{%0,%1,%2,%3};\n"
        : "+f"(c[0]), "+f"(c[1]), "+f"(c[2]), "+f"(c[3])
        : "r"(a[0]), "r"(a[1]), "r"(a[2]), "r"(a[3]), "r"(b0), "r"(b1));
}

// ---------------------------------------------------------------------------
// FP16 tensor-core NT GEMM: C[M,N] = A[M,K] @ B[N,K]^T + bias[N]   (fp32 acc)
// CTA tile 128x128, BK=64 fp16, 3-stage cp.async, one barrier per k-iter.
// 128 threads = 4 warps (2m x 2n), warp tile 64x64. 2 CTAs/SM.
// ---------------------------------------------------------------------------
#define BM 128
#define BN 128
#define BK 64
#define STAGES 3
#define ROWB 144
#define STAGE_BYTES (BM * ROWB)                       // 18432
#define GEMM_SMEM   (STAGES * STAGE_BYTES * 2)        // 110592

template<bool HOUT>
__global__ void __launch_bounds__(128, 2)
gemm_nt_f16(const __half* __restrict__ A, const __half* __restrict__ Bm,
            const float* __restrict__ bias, void* __restrict__ Cv,
            int M, int N, int K)
{
    extern __shared__ char smc[];
    const uint32_t smA = (uint32_t)__cvta_generic_to_shared(smc);
    const uint32_t smB = smA + STAGES * STAGE_BYTES;

    const int tid  = threadIdx.x;
    const int bm   = blockIdx.y * BM;
    const int bn   = blockIdx.x * BN;
    const int warp = tid >> 5;
    const int lane = tid & 31;
    const int wm   = warp >> 1;
    const int wn   = warp & 1;

    const __half* AgP[8]; uint32_t sAP[8];
    const __half* BgP[8]; uint32_t sBP[8];
#pragma unroll
    for (int i = 0; i < 8; i++) {
        const int c   = tid + i * 128;
        const int row = c >> 3;
        const int ch  = c & 7;
        AgP[i] = A  + (size_t)(bm + row) * K + ch * 8;
        BgP[i] = Bm + (size_t)(bn + row) * K + ch * 8;
        sAP[i] = smA + (uint32_t)(row * ROWB + ch * 16);
        sBP[i] = smB + (uint32_t)(row * ROWB + ch * 16);
    }

    const int lrow = lane & 15;
    const int lkb  = (lane >> 4) * 16;
    const uint32_t aFrag = smA + (uint32_t)((wm * 64 + lrow) * ROWB + lkb);
    const uint32_t bFrag = smB + (uint32_t)((wn * 64 + lrow) * ROWB + lkb);

    float c[4][8][4];
#pragma unroll
    for (int i = 0; i < 4; i++)
#pragma unroll
        for (int j = 0; j < 8; j++)
#pragma unroll
            for (int r = 0; r < 4; r++) c[i][j][r] = 0.0f;

    const int NT = K / BK;

#pragma unroll
    for (int p = 0; p < STAGES - 1; p++) {
        const int koff = p * BK;
        const uint32_t so = (uint32_t)(p * STAGE_BYTES);
#pragma unroll
        for (int i = 0; i < 8; i++) {
            cp16(sAP[i] + so, AgP[i] + koff);
            cp16(sBP[i] + so, BgP[i] + koff);
        }
        cp_commit();
    }

    int st = 0;
    for (int s = 0; s < NT; s++) {
        if (s + 1 < NT) {
            asm volatile("cp.async.wait_group 1;\n");
        } else {
            asm volatile("cp.async.wait_group 0;\n");
        }
        __syncthreads();

        if (s + STAGES - 1 < NT) {
            const int koff = (s + STAGES - 1) * BK;
            const int slot = (s + STAGES - 1) % STAGES;
            const uint32_t so = (uint32_t)(slot * STAGE_BYTES);
#pragma unroll
            for (int i = 0; i < 8; i++) {
                cp16(sAP[i] + so, AgP[i] + koff);
                cp16(sBP[i] + so, BgP[i] + koff);
            }
            cp_commit();
        }

        {
            const uint32_t aOff = aFrag + (uint32_t)(st * STAGE_BYTES);
            const uint32_t bOff = bFrag + (uint32_t)(st * STAGE_BYTES);
#pragma unroll
            for (int kk = 0; kk < 4; kk++) {
                uint32_t a[4][4];
#pragma unroll
                for (int am = 0; am < 4; am++)
                    ldsm4(a[am], aOff + kk * 32 + am * (16 * ROWB));
                uint32_t b[4][4];
#pragma unroll
                for (int pr = 0; pr < 4; pr++)
                    ldsm4(b[pr], bOff + kk * 32 + pr * (16 * ROWB));
#pragma unroll
                for (int am = 0; am < 4; am++)
#pragma unroll
                    for (int an = 0; an < 8; an++)
                        mma_f16(c[am][an], a[am],
                                b[an >> 1][an & 1], b[an >> 1][2 + (an & 1)]);
            }
        }
        st = (st + 1 == STAGES) ? 0 : st + 1;
    }

    const int erow = lane >> 2;
    const int ecol = (lane & 3) * 2;
#pragma unroll
    for (int am = 0; am < 4; am++) {
        const int row = bm + wm * 64 + am * 16 + erow;
#pragma unroll
        for (int an = 0; an < 8; an++) {
            const int col = bn + wn * 64 + an * 8 + ecol;
            const float b0v = __ldg(bias + col);
            const float b1v = __ldg(bias + col + 1);
            if (HOUT) {
                __half* C = (__half*)Cv;
                __half2 v0 = __floats2half2_rn(c[am][an][0] + b0v, c[am][an][1] + b1v);
                __half2 v1 = __floats2half2_rn(c[am][an][2] + b0v, c[am][an][3] + b1v);
                *(__half2*)(C + (size_t)row * N + col) = v0;
                *(__half2*)(C + (size_t)(row + 8) * N + col) = v1;
            } else {
                float* C = (float*)Cv;
                float* p0 = C + (size_t)row * N + col;
                float* p1 = C + (size_t)(row + 8) * N + col;
                p0[0] = c[am][an][0] + b0v;
                p0[1] = c[am][an][1] + b1v;
                p1[0] = c[am][an][2] + b0v;
                p1[1] = c[am][an][3] + b1v;
            }
        }
    }
}

// ---------------------------------------------------------------------------
// Tensor-core attention per (batch, head). 128 threads = 4 warps.
// ---------------------------------------------------------------------------
#define QROWB 272
#define PROWB 144
#define PS_PAD 65
#define OFF_Q 0
#define OFF_K 17408
#define OFF_V 34816
#define OFF_P 52224
#define ATTN_SMEM (OFF_P + SEQ * PS_PAD * 4)   // 68864

__global__ void __launch_bounds__(128)
attn64(const __half* __restrict__ qkv, __half* __restrict__ att)
{
    extern __shared__ char smc[];
    const uint32_t sb  = (uint32_t)__cvta_generic_to_shared(smc);
    const uint32_t smQ = sb + OFF_Q;
    const uint32_t smK = sb + OFF_K;
    const uint32_t smV = sb + OFF_V;
    float* Ps = (float*)(smc + OFF_P);

    const int bh   = blockIdx.x;
    const int b    = bh >> 4;
    const int h    = bh & 15;
    const int tid  = threadIdx.x;
    const int warp = tid >> 5;
    const int lane = tid & 31;

    const __half* base = qkv + (size_t)b * SEQ * E3 + h * HD;

#pragma unroll
    for (int i = 0; i < 8; i++) {
        const int c   = tid + i * 128;
        const int row = c >> 4;
        const int ch  = c & 15;
        const __half* src = base + (size_t)row * E3 + ch * 8;
        const uint32_t d  = (uint32_t)(row * QROWB + ch * 16);
        cp16(smQ + d, src);
        cp16(smK + d, src + DMODEL);
        cp16(smV + d, src + 2 * DMODEL);
    }
    cp_commit();
    asm volatile("cp.async.wait_group 0;\n");
    __syncthreads();

    const int lrow = lane & 15;
    const int lkb  = (lane >> 4) * 16;
    const int erow = lane >> 2;
    const int ecol = (lane & 3) * 2;

    // ---- QK^T ----
    {
        const uint32_t aBase = smQ + (uint32_t)((warp * 16 + lrow) * QROWB + lkb);
        float scc[8][4];
#pragma unroll
        for (int j = 0; j < 8; j++)
#pragma unroll
            for (int r = 0; r < 4; r++) scc[j][r] = 0.0f;

#pragma unroll
        for (int kk = 0; kk < 8; kk++) {
            uint32_t a[4];
            ldsm4(a, aBase + kk * 32);
            uint32_t bb[4][4];
#pragma unroll
            for (int pr = 0; pr < 4; pr++)
                ldsm4(bb[pr], smK + (uint32_t)((pr * 16 + lrow) * QROWB + lkb) + kk * 32);
#pragma unroll
            for (int an = 0; an < 8; an++)
                mma_f16(scc[an], a, bb[an >> 1][an & 1], bb[an >> 1][2 + (an & 1)]);
        }

        const float scale = 0.022097086912079608f;  // 1/sqrt(2048)
#pragma unroll
        for (int an = 0; an < 8; an++) {
            const int q0 = warp * 16 + erow;
            const int q1 = q0 + 8;
            const int k0 = an * 8 + ecol;
            Ps[q0 * PS_PAD + k0]     = (k0     <= q0) ? scc[an][0] * scale : -1e30f;
            Ps[q0 * PS_PAD + k0 + 1] = (k0 + 1 <= q0) ? scc[an][1] * scale : -1e30f;
            Ps[q1 * PS_PAD + k0]     = (k0     <= q1) ? scc[an][2] * scale : -1e30f;
            Ps[q1 * PS_PAD + k0 + 1] = (k0 + 1 <= q1) ? scc[an][3] * scale : -1e30f;
        }
    }
    __syncthreads();

    // ---- column softmax over q (axis=-2) ----
    if (tid < SEQ) {
        const int k = tid;
        float m = -1e30f;
        for (int q = k; q < SEQ; q++) m = fmaxf(m, Ps[q * PS_PAD + k]);
        float ssum = 0.0f;
        for (int q = k; q < SEQ; q++) {
            float e = __expf(Ps[q * PS_PAD + k] - m);
            Ps[q * PS_PAD + k] = e;
            ssum += e;
        }
        const float inv = 1.0f / ssum;
        for (int q = 0; q < SEQ; q++)
            Ps[q * PS_PAD + k] = (q < k) ? 0.0f : Ps[q * PS_PAD + k] * inv;
    }
    __syncthreads();

    // ---- P -> fp16 (reuse Q region) ----
    {
        const int r  = tid >> 1;
        const int cb = (tid & 1) * 32;
#pragma unroll
        for (int j = 0; j < 32; j += 2) {
            __half2 hp = __floats2half2_rn(Ps[r * PS_PAD + cb + j],
                                           Ps[r * PS_PAD + cb + j + 1]);
            *(__half2*)(smc + OFF_Q + r * PROWB + (cb + j) * 2) = hp;
        }
    }
    __syncthreads();

    // ---- PV with ldmatrix.trans on V ----
    {
        const uint32_t aBase = smQ + (uint32_t)((warp * 16 + lrow) * PROWB + lkb);
        const int vrow_off = ((lane >> 4) & 1) * 8 + (lane & 7);
        const int vcol_off = ((lane >> 3) & 1) * 8;

        float pacc[16][4];
#pragma unroll
        for (int j = 0; j < 16; j++)
#pragma unroll
            for (int r = 0; r < 4; r++) pacc[j][r] = 0.0f;

#pragma unroll
        for (int kk = 0; kk < 4; kk++) {
            uint32_t a[4];
            ldsm4(a, aBase + kk * 32);
#pragma unroll
            for (int g = 0; g < 8; g++) {
                uint32_t vb[4];
                ldsm4t(vb, smV + (uint32_t)((kk * 16 + vrow_off) * QROWB
                                            + (g * 16 + vcol_off) * 2));
                mma_f16(pacc[2 * g],     a, vb[0], vb[2]);
                mma_f16(pacc[2 * g + 1], a, vb[1], vb[3]);
            }
        }

        __half* outp = att + (size_t)b * SEQ * DMODEL + h * HD;
        const int q0 = warp * 16 + erow;
        const int q1 = q0 + 8;
#pragma unroll
        for (int at = 0; at < 16; at++) {
            const int c0 = (at >> 1) * 16 + (at & 1) * 8 + ecol;
            __half2 v0 = __floats2half2_rn(pacc[at][0], pacc[at][1]);
            __half2 v1 = __floats2half2_rn(pacc[at][2], pacc[at][3]);
            *(__half2*)(outp + (size_t)q0 * DMODEL + c0) = v0;
            *(__half2*)(outp + (size_t)q1 * DMODEL + c0) = v1;
        }
    }
}

// ---------------------------------------------------------------------------
// Launch: 4-chunk M pipeline. s0 streams GEMM1 chunks; s2 chases with
// attention + GEMM3 per chunk. Only chunk 3's attn+GEMM3 stay exposed.
// Capture-legal (event fork/join, no allocs).
// ---------------------------------------------------------------------------
#define NCH   4
#define M_CH  (TOK / NCH)       // 4096 tokens
#define B_CH  (NBATCH / NCH)    // 64 batches

extern "C" void kernel_launch(void* const* d_in, const int* in_sizes, int n_in,
                              void* d_out, int out_size)
{
    const float* x     = (const float*)d_in[0];
    const float* W_qkv = (const float*)d_in[1];
    const float* b_qkv = (const float*)d_in[2];
    const float* W_out = (const float*)d_in[3];
    const float* b_out = (const float*)d_in[4];
    float* out = (float*)d_out;

    __half *qkvh = nullptr, *att = nullptr, *xh = nullptr, *wqh = nullptr, *woh = nullptr;
    cudaGetSymbolAddress((void**)&qkvh, g_qkvh);
    cudaGetSymbolAddress((void**)&att,  g_att);
    cudaGetSymbolAddress((void**)&xh,   g_xh);
    cudaGetSymbolAddress((void**)&wqh,  g_wqh);
    cudaGetSymbolAddress((void**)&woh,  g_woh);

    cudaFuncSetAttribute(gemm_nt_f16<true>,  cudaFuncAttributeMaxDynamicSharedMemorySize, GEMM_SMEM);
    cudaFuncSetAttribute(gemm_nt_f16<false>, cudaFuncAttributeMaxDynamicSharedMemorySize, GEMM_SMEM);
    cudaFuncSetAttribute(attn64, cudaFuncAttributeMaxDynamicSharedMemorySize, ATTN_SMEM);

    // one-time stream/event creation (host objects; no device allocations)
    static cudaStream_t s2 = nullptr;
    static cudaEvent_t e0 = nullptr, eC = nullptr;
    static cudaEvent_t eG[NCH] = {};
    if (!s2) {
        cudaStreamCreateWithFlags(&s2, cudaStreamNonBlocking);
        cudaEventCreateWithFlags(&e0, cudaEventDisableTiming);
        cudaEventCreateWithFlags(&eC, cudaEventDisableTiming);
        for (int c = 0; c < NCH; c++)
            cudaEventCreateWithFlags(&eG[c], cudaEventDisableTiming);
    }

    // fork s2 from origin stream
    cudaEventRecord(e0, 0);
    cudaStreamWaitEvent(s2, e0, 0);

    // s2: convert W_out (runs under s0's converters)
    {
        int n4o = DMODEL * DMODEL / 4;
        f2h_kernel<<<n4o / 256, 256, 0, s2>>>((const float4*)W_out, (uint2*)woh, n4o);
    }

    // s0: convert x and W_qkv (both needed by GEMM1)
    {
        int n4x = TOK * DMODEL / 4;
        f2h_kernel<<<n4x / 256, 256>>>((const float4*)x, (uint2*)xh, n4x);
        int n4q = E3 * DMODEL / 4;
        f2h_kernel<<<n4q / 256, 256>>>((const float4*)W_qkv, (uint2*)wqh, n4q);
    }

    // s0: GEMM1 chunks, each followed by an event for s2 to chase
    for (int c = 0; c < NCH; c++) {
        dim3 grid(E3 / BN, M_CH / BM);   // 48 x 32
        gemm_nt_f16<true><<<grid, 128, GEMM_SMEM>>>(
            xh + (size_t)c * M_CH * DMODEL, wqh, b_qkv,
            qkvh + (size_t)c * M_CH * E3, M_CH, E3, DMODEL);
        cudaEventRecord(eG[c], 0);
    }

    // s2: per chunk: attention then GEMM3 (convWo already ordered on s2)
    for (int c = 0; c < NCH; c++) {
        cudaStreamWaitEvent(s2, eG[c], 0);
        attn64<<<B_CH * NHEAD, 128, ATTN_SMEM, s2>>>(
            qkvh + (size_t)c * B_CH * SEQ * E3,
            att + (size_t)c * M_CH * DMODEL);
        dim3 grid(DMODEL / BN, M_CH / BM);   // 16 x 32
        gemm_nt_f16<false><<<grid, 128, GEMM_SMEM, s2>>>(
            att + (size_t)c * M_CH * DMODEL, woh, b_out,
            out + (size_t)c * M_CH * DMODEL, M_CH, DMODEL, DMODEL);
    }
    cudaEventRecord(eC, s2);

    // join s2 back into origin stream
    cudaStreamWaitEvent(0, eC, 0);
}

// round 17
// speedup vs baseline: 1.0207x; 1.0207x over previous
#include <cuda_runtime.h>
#include <cuda_fp16.h>
#include <stdint.h>
#include <math.h>

// ---------------------------------------------------------------------------
// Problem constants
// ---------------------------------------------------------------------------
#define TOK      16384
#define DMODEL   2048
#define E3       6144
#define NHEAD    16
#define HD       128
#define SEQ      64
#define NBATCH   256

// Scratch (device globals: allocation rules forbid cudaMalloc)
__device__ __half g_qkvh[(size_t)TOK * E3];         // GEMM1 out, fp16
__device__ __half g_att[(size_t)TOK * DMODEL];      // attention out, fp16
__device__ __half g_xh [(size_t)TOK * DMODEL];      // x -> fp16
__device__ __half g_wqh[(size_t)E3  * DMODEL];      // W_qkv -> fp16
__device__ __half g_woh[(size_t)DMODEL * DMODEL];   // W_out -> fp16

// ---------------------------------------------------------------------------
// fp32 -> fp16 (rn) conversion
// ---------------------------------------------------------------------------
__global__ void __launch_bounds__(256)
f2h_kernel(const float4* __restrict__ in, uint2* __restrict__ out, int n4)
{
    int i = blockIdx.x * blockDim.x + threadIdx.x;
    if (i < n4) {
        float4 v = in[i];
        __half2 h0 = __floats2half2_rn(v.x, v.y);
        __half2 h1 = __floats2half2_rn(v.z, v.w);
        uint2 u;
        u.x = *(uint32_t*)&h0;
        u.y = *(uint32_t*)&h1;
        out[i] = u;
    }
}

// ---------------------------------------------------------------------------
// Common PTX helpers
// ---------------------------------------------------------------------------
__device__ __forceinline__ void cp16(uint32_t dst, const __half* src) {
    asm volatile("cp.async.cg.shared.global [%0], [%1], 16;\n" :: "r"(dst), "l"(src));
}
__device__ __forceinline__ void cp_commit() {
    asm volatile("cp.async.commit_group;\n");
}
__device__ __forceinline__ void ldsm4(uint32_t (&r)[4], uint32_t addr) {
    asm volatile("ldmatrix.sync.aligned.m8n8.x4.shared.b16 {%0,%1,%2,%3}, [%4];\n"
                 : "=r"(r[0]), "=r"(r[1]), "=r"(r[2]), "=r"(r[3]) : "r"(addr));
}
__device__ __forceinline__ void ldsm4t(uint32_t (&r)[4], uint32_t addr) {
    asm volatile("ldmatrix.sync.aligned.m8n8.x4.trans.shared.b16 {%0,%1,%2,%3}, [%4];\n"
                 : "=r"(r[0]), "=r"(r[1]), "=r"(r[2]), "=r"(r[3]) : "r"(addr));
}
__device__ __forceinline__ void mma_f16(float (&c)[4], const uint32_t (&a)[4],
                                        uint32_t b0, uint32_t b1) {
    asm volatile(
        "mma.sync.aligned.m16n8k16.row.col.f32.f16.f16.f32 "
        "{%0,%1,%2,%3},{%4,%5,%6,%7},{%8,%9},{%0,%1,%2,%3};\n"
        : "+f"(c[0]), "+f"(c[1]), "+f"(c[2]), "+f"(c[3])
        : "r"(a[0]), "r"(a[1]), "r"(a[2]), "r"(a[3]), "r"(b0), "r"(b1));
}

// ---------------------------------------------------------------------------
// FP16 tensor-core NT GEMM: C[M,N] = A[M,K] @ B[N,K]^T + bias[N]   (fp32 acc)
// CTA tile 128x128, BK=64 fp16, 3-stage cp.async, one barrier per k-iter.
// 128 threads = 4 warps (2m x 2n), warp tile 64x64. 2 CTAs/SM.
// ---------------------------------------------------------------------------
#define BM 128
#define BN 128
#define BK 64
#define STAGES 3
#define ROWB 144
#define STAGE_BYTES (BM * ROWB)                       // 18432
#define GEMM_SMEM   (STAGES * STAGE_BYTES * 2)        // 110592

template<bool HOUT>
__global__ void __launch_bounds__(128, 2)
gemm_nt_f16(const __half* __restrict__ A, const __half* __restrict__ Bm,
            const float* __restrict__ bias, void* __restrict__ Cv,
            int M, int N, int K)
{
    extern __shared__ char smc[];
    const uint32_t smA = (uint32_t)__cvta_generic_to_shared(smc);
    const uint32_t smB = smA + STAGES * STAGE_BYTES;

    const int tid  = threadIdx.x;
    const int bm   = blockIdx.y * BM;
    const int bn   = blockIdx.x * BN;
    const int warp = tid >> 5;
    const int lane = tid & 31;
    const int wm   = warp >> 1;
    const int wn   = warp & 1;

    const __half* AgP[8]; uint32_t sAP[8];
    const __half* BgP[8]; uint32_t sBP[8];
#pragma unroll
    for (int i = 0; i < 8; i++) {
        const int c   = tid + i * 128;
        const int row = c >> 3;
        const int ch  = c & 7;
        AgP[i] = A  + (size_t)(bm + row) * K + ch * 8;
        BgP[i] = Bm + (size_t)(bn + row) * K + ch * 8;
        sAP[i] = smA + (uint32_t)(row * ROWB + ch * 16);
        sBP[i] = smB + (uint32_t)(row * ROWB + ch * 16);
    }

    const int lrow = lane & 15;
    const int lkb  = (lane >> 4) * 16;
    const uint32_t aFrag = smA + (uint32_t)((wm * 64 + lrow) * ROWB + lkb);
    const uint32_t bFrag = smB + (uint32_t)((wn * 64 + lrow) * ROWB + lkb);

    float c[4][8][4];
#pragma unroll
    for (int i = 0; i < 4; i++)
#pragma unroll
        for (int j = 0; j < 8; j++)
#pragma unroll
            for (int r = 0; r < 4; r++) c[i][j][r] = 0.0f;

    const int NT = K / BK;

#pragma unroll
    for (int p = 0; p < STAGES - 1; p++) {
        const int koff = p * BK;
        const uint32_t so = (uint32_t)(p * STAGE_BYTES);
#pragma unroll
        for (int i = 0; i < 8; i++) {
            cp16(sAP[i] + so, AgP[i] + koff);
            cp16(sBP[i] + so, BgP[i] + koff);
        }
        cp_commit();
    }

    int st = 0;
    for (int s = 0; s < NT; s++) {
        if (s + 1 < NT) {
            asm volatile("cp.async.wait_group 1;\n");
        } else {
            asm volatile("cp.async.wait_group 0;\n");
        }
        __syncthreads();

        if (s + STAGES - 1 < NT) {
            const int koff = (s + STAGES - 1) * BK;
            const int slot = (s + STAGES - 1) % STAGES;
            const uint32_t so = (uint32_t)(slot * STAGE_BYTES);
#pragma unroll
            for (int i = 0; i < 8; i++) {
                cp16(sAP[i] + so, AgP[i] + koff);
                cp16(sBP[i] + so, BgP[i] + koff);
            }
            cp_commit();
        }

        {
            const uint32_t aOff = aFrag + (uint32_t)(st * STAGE_BYTES);
            const uint32_t bOff = bFrag + (uint32_t)(st * STAGE_BYTES);
#pragma unroll
            for (int kk = 0; kk < 4; kk++) {
                uint32_t a[4][4];
#pragma unroll
                for (int am = 0; am < 4; am++)
                    ldsm4(a[am], aOff + kk * 32 + am * (16 * ROWB));
                uint32_t b[4][4];
#pragma unroll
                for (int pr = 0; pr < 4; pr++)
                    ldsm4(b[pr], bOff + kk * 32 + pr * (16 * ROWB));
#pragma unroll
                for (int am = 0; am < 4; am++)
#pragma unroll
                    for (int an = 0; an < 8; an++)
                        mma_f16(c[am][an], a[am],
                                b[an >> 1][an & 1], b[an >> 1][2 + (an & 1)]);
            }
        }
        st = (st + 1 == STAGES) ? 0 : st + 1;
    }

    const int erow = lane >> 2;
    const int ecol = (lane & 3) * 2;
#pragma unroll
    for (int am = 0; am < 4; am++) {
        const int row = bm + wm * 64 + am * 16 + erow;
#pragma unroll
        for (int an = 0; an < 8; an++) {
            const int col = bn + wn * 64 + an * 8 + ecol;
            const float b0v = __ldg(bias + col);
            const float b1v = __ldg(bias + col + 1);
            if (HOUT) {
                __half* C = (__half*)Cv;
                __half2 v0 = __floats2half2_rn(c[am][an][0] + b0v, c[am][an][1] + b1v);
                __half2 v1 = __floats2half2_rn(c[am][an][2] + b0v, c[am][an][3] + b1v);
                *(__half2*)(C + (size_t)row * N + col) = v0;
                *(__half2*)(C + (size_t)(row + 8) * N + col) = v1;
            } else {
                float* C = (float*)Cv;
                float* p0 = C + (size_t)row * N + col;
                float* p1 = C + (size_t)(row + 8) * N + col;
                p0[0] = c[am][an][0] + b0v;
                p0[1] = c[am][an][1] + b1v;
                p1[0] = c[am][an][2] + b0v;
                p1[1] = c[am][an][3] + b1v;
            }
        }
    }
}

// ---------------------------------------------------------------------------
// Tensor-core attention per (batch, head). 128 threads = 4 warps.
// ---------------------------------------------------------------------------
#define QROWB 272
#define PROWB 144
#define PS_PAD 65
#define OFF_Q 0
#define OFF_K 17408
#define OFF_V 34816
#define OFF_P 52224
#define ATTN_SMEM (OFF_P + SEQ * PS_PAD * 4)   // 68864

__global__ void __launch_bounds__(128)
attn64(const __half* __restrict__ qkv, __half* __restrict__ att)
{
    extern __shared__ char smc[];
    const uint32_t sb  = (uint32_t)__cvta_generic_to_shared(smc);
    const uint32_t smQ = sb + OFF_Q;
    const uint32_t smK = sb + OFF_K;
    const uint32_t smV = sb + OFF_V;
    float* Ps = (float*)(smc + OFF_P);

    const int bh   = blockIdx.x;
    const int b    = bh >> 4;
    const int h    = bh & 15;
    const int tid  = threadIdx.x;
    const int warp = tid >> 5;
    const int lane = tid & 31;

    const __half* base = qkv + (size_t)b * SEQ * E3 + h * HD;

#pragma unroll
    for (int i = 0; i < 8; i++) {
        const int c   = tid + i * 128;
        const int row = c >> 4;
        const int ch  = c & 15;
        const __half* src = base + (size_t)row * E3 + ch * 8;
        const uint32_t d  = (uint32_t)(row * QROWB + ch * 16);
        cp16(smQ + d, src);
        cp16(smK + d, src + DMODEL);
        cp16(smV + d, src + 2 * DMODEL);
    }
    cp_commit();
    asm volatile("cp.async.wait_group 0;\n");
    __syncthreads();

    const int lrow = lane & 15;
    const int lkb  = (lane >> 4) * 16;
    const int erow = lane >> 2;
    const int ecol = (lane & 3) * 2;

    // ---- QK^T ----
    {
        const uint32_t aBase = smQ + (uint32_t)((warp * 16 + lrow) * QROWB + lkb);
        float scc[8][4];
#pragma unroll
        for (int j = 0; j < 8; j++)
#pragma unroll
            for (int r = 0; r < 4; r++) scc[j][r] = 0.0f;

#pragma unroll
        for (int kk = 0; kk < 8; kk++) {
            uint32_t a[4];
            ldsm4(a, aBase + kk * 32);
            uint32_t bb[4][4];
#pragma unroll
            for (int pr = 0; pr < 4; pr++)
                ldsm4(bb[pr], smK + (uint32_t)((pr * 16 + lrow) * QROWB + lkb) + kk * 32);
#pragma unroll
            for (int an = 0; an < 8; an++)
                mma_f16(scc[an], a, bb[an >> 1][an & 1], bb[an >> 1][2 + (an & 1)]);
        }

        const float scale = 0.022097086912079608f;  // 1/sqrt(2048)
#pragma unroll
        for (int an = 0; an < 8; an++) {
            const int q0 = warp * 16 + erow;
            const int q1 = q0 + 8;
            const int k0 = an * 8 + ecol;
            Ps[q0 * PS_PAD + k0]     = (k0     <= q0) ? scc[an][0] * scale : -1e30f;
            Ps[q0 * PS_PAD + k0 + 1] = (k0 + 1 <= q0) ? scc[an][1] * scale : -1e30f;
            Ps[q1 * PS_PAD + k0]     = (k0     <= q1) ? scc[an][2] * scale : -1e30f;
            Ps[q1 * PS_PAD + k0 + 1] = (k0 + 1 <= q1) ? scc[an][3] * scale : -1e30f;
        }
    }
    __syncthreads();

    // ---- column softmax over q (axis=-2) ----
    if (tid < SEQ) {
        const int k = tid;
        float m = -1e30f;
        for (int q = k; q < SEQ; q++) m = fmaxf(m, Ps[q * PS_PAD + k]);
        float ssum = 0.0f;
        for (int q = k; q < SEQ; q++) {
            float e = __expf(Ps[q * PS_PAD + k] - m);
            Ps[q * PS_PAD + k] = e;
            ssum += e;
        }
        const float inv = 1.0f / ssum;
        for (int q = 0; q < SEQ; q++)
            Ps[q * PS_PAD + k] = (q < k) ? 0.0f : Ps[q * PS_PAD + k] * inv;
    }
    __syncthreads();

    // ---- P -> fp16 (reuse Q region) ----
    {
        const int r  = tid >> 1;
        const int cb = (tid & 1) * 32;
#pragma unroll
        for (int j = 0; j < 32; j += 2) {
            __half2 hp = __floats2half2_rn(Ps[r * PS_PAD + cb + j],
                                           Ps[r * PS_PAD + cb + j + 1]);
            *(__half2*)(smc + OFF_Q + r * PROWB + (cb + j) * 2) = hp;
        }
    }
    __syncthreads();

    // ---- PV with ldmatrix.trans on V ----
    {
        const uint32_t aBase = smQ + (uint32_t)((warp * 16 + lrow) * PROWB + lkb);
        const int vrow_off = ((lane >> 4) & 1) * 8 + (lane & 7);
        const int vcol_off = ((lane >> 3) & 1) * 8;

        float pacc[16][4];
#pragma unroll
        for (int j = 0; j < 16; j++)
#pragma unroll
            for (int r = 0; r < 4; r++) pacc[j][r] = 0.0f;

#pragma unroll
        for (int kk = 0; kk < 4; kk++) {
            uint32_t a[4];
            ldsm4(a, aBase + kk * 32);
#pragma unroll
            for (int g = 0; g < 8; g++) {
                uint32_t vb[4];
                ldsm4t(vb, smV + (uint32_t)((kk * 16 + vrow_off) * QROWB
                                            + (g * 16 + vcol_off) * 2));
                mma_f16(pacc[2 * g],     a, vb[0], vb[2]);
                mma_f16(pacc[2 * g + 1], a, vb[1], vb[3]);
            }
        }

        __half* outp = att + (size_t)b * SEQ * DMODEL + h * HD;
        const int q0 = warp * 16 + erow;
        const int q1 = q0 + 8;
#pragma unroll
        for (int at = 0; at < 16; at++) {
            const int c0 = (at >> 1) * 16 + (at & 1) * 8 + ecol;
            __half2 v0 = __floats2half2_rn(pacc[at][0], pacc[at][1]);
            __half2 v1 = __floats2half2_rn(pacc[at][2], pacc[at][3]);
            *(__half2*)(outp + (size_t)q0 * DMODEL + c0) = v0;
            *(__half2*)(outp + (size_t)q1 * DMODEL + c0) = v1;
        }
    }
}

// ---------------------------------------------------------------------------
// Launch: 2-way M-split. Schedule hides ALL attention under GEMM work:
//   s0: convX | G1_lo | G1_hi | G3_lo            | G3_hi
//   s2: convWq,convWo |  attn_lo (under G1_hi)   | attn_hi (under G3_lo)
// ---------------------------------------------------------------------------
#define M_HALF (TOK / 2)   // 8192 tokens = 128 batches

extern "C" void kernel_launch(void* const* d_in, const int* in_sizes, int n_in,
                              void* d_out, int out_size)
{
    const float* x     = (const float*)d_in[0];
    const float* W_qkv = (const float*)d_in[1];
    const float* b_qkv = (const float*)d_in[2];
    const float* W_out = (const float*)d_in[3];
    const float* b_out = (const float*)d_in[4];
    float* out = (float*)d_out;

    __half *qkvh = nullptr, *att = nullptr, *xh = nullptr, *wqh = nullptr, *woh = nullptr;
    cudaGetSymbolAddress((void**)&qkvh, g_qkvh);
    cudaGetSymbolAddress((void**)&att,  g_att);
    cudaGetSymbolAddress((void**)&xh,   g_xh);
    cudaGetSymbolAddress((void**)&wqh,  g_wqh);
    cudaGetSymbolAddress((void**)&woh,  g_woh);

    cudaFuncSetAttribute(gemm_nt_f16<true>,  cudaFuncAttributeMaxDynamicSharedMemorySize, GEMM_SMEM);
    cudaFuncSetAttribute(gemm_nt_f16<false>, cudaFuncAttributeMaxDynamicSharedMemorySize, GEMM_SMEM);
    cudaFuncSetAttribute(attn64, cudaFuncAttributeMaxDynamicSharedMemorySize, ATTN_SMEM);

    // one-time stream/event creation (host objects; no device allocations)
    static cudaStream_t s2 = nullptr;
    static cudaEvent_t e0 = nullptr, eWq = nullptr, eA = nullptr, eB = nullptr,
                       eAL = nullptr, eAH = nullptr;
    if (!s2) {
        cudaStreamCreateWithFlags(&s2, cudaStreamNonBlocking);
        cudaEventCreateWithFlags(&e0,  cudaEventDisableTiming);
        cudaEventCreateWithFlags(&eWq, cudaEventDisableTiming);
        cudaEventCreateWithFlags(&eA,  cudaEventDisableTiming);
        cudaEventCreateWithFlags(&eB,  cudaEventDisableTiming);
        cudaEventCreateWithFlags(&eAL, cudaEventDisableTiming);
        cudaEventCreateWithFlags(&eAH, cudaEventDisableTiming);
    }

    // fork s2 from origin stream
    cudaEventRecord(e0, 0);
    cudaStreamWaitEvent(s2, e0, 0);

    // s2: weight conversions (parallel with s0's convX)
    {
        int n4q = E3 * DMODEL / 4;
        f2h_kernel<<<n4q / 256, 256, 0, s2>>>((const float4*)W_qkv, (uint2*)wqh, n4q);
        cudaEventRecord(eWq, s2);
        int n4o = DMODEL * DMODEL / 4;
        f2h_kernel<<<n4o / 256, 256, 0, s2>>>((const float4*)W_out, (uint2*)woh, n4o);
    }

    // s0: convert x
    {
        int n4x = TOK * DMODEL / 4;
        f2h_kernel<<<n4x / 256, 256>>>((const float4*)x, (uint2*)xh, n4x);
    }

    // s0: GEMM1 lo, GEMM1 hi
    {
        cudaStreamWaitEvent(0, eWq, 0);
        dim3 grid(E3 / BN, M_HALF / BM);   // 48 x 64 = 3072 CTAs
        gemm_nt_f16<true><<<grid, 128, GEMM_SMEM>>>(xh, wqh, b_qkv, qkvh,
                                                    M_HALF, E3, DMODEL);
        cudaEventRecord(eA, 0);
        gemm_nt_f16<true><<<grid, 128, GEMM_SMEM>>>(
            xh + (size_t)M_HALF * DMODEL, wqh, b_qkv,
            qkvh + (size_t)M_HALF * E3, M_HALF, E3, DMODEL);
        cudaEventRecord(eB, 0);
    }

    // s2: attn_lo (hidden under G1_hi), then attn_hi (hidden under G3_lo)
    {
        cudaStreamWaitEvent(s2, eA, 0);
        attn64<<<(NBATCH / 2) * NHEAD, 128, ATTN_SMEM, s2>>>(qkvh, att);
        cudaEventRecord(eAL, s2);    // also orders convWo (stream-ordered on s2)
        cudaStreamWaitEvent(s2, eB, 0);
        attn64<<<(NBATCH / 2) * NHEAD, 128, ATTN_SMEM, s2>>>(
            qkvh + (size_t)(NBATCH / 2) * SEQ * E3,
            att + (size_t)M_HALF * DMODEL);
        cudaEventRecord(eAH, s2);
    }

    // s0: GEMM3 lo (runs while attn_hi runs on s2), then GEMM3 hi
    {
        cudaStreamWaitEvent(0, eAL, 0);
        dim3 grid(DMODEL / BN, M_HALF / BM);   // 16 x 64 = 1024 CTAs
        gemm_nt_f16<false><<<grid, 128, GEMM_SMEM>>>(att, woh, b_out, out,
                                                     M_HALF, DMODEL, DMODEL);
        cudaStreamWaitEvent(0, eAH, 0);
        gemm_nt_f16<false><<<grid, 128, GEMM_SMEM>>>(
            att + (size_t)M_HALF * DMODEL, woh, b_out,
            out + (size_t)M_HALF * DMODEL, M_HALF, DMODEL, DMODEL);
    }
}